// round 1
// baseline (speedup 1.0000x reference)
#include <cuda_runtime.h>
#include <cuda_bf16.h>

#define N_NODES 100000
#define N_EDGES 1600000
#define D 48
#define D4 (D / 4)   // 12 float4 chunks per row

// Scratch for xw = x @ w  (19.2 MB) — __device__ global, no allocation.
__device__ float g_xw[N_NODES * D];

// ---------------------------------------------------------------------------
// Zero the output buffer (it is poisoned to 0xAA by the harness).
// ---------------------------------------------------------------------------
__global__ void zero_kernel(float4* __restrict__ out) {
    int i = blockIdx.x * blockDim.x + threadIdx.x;
    int total = N_NODES * D4;
    if (i < total) out[i] = make_float4(0.f, 0.f, 0.f, 0.f);
}

// ---------------------------------------------------------------------------
// Dense GEMM: g_xw[n][j] = sum_k x[n][k] * w[k][j].
// One thread per node row. w cached in shared memory (9.2 KB).
// ---------------------------------------------------------------------------
__global__ void gemm_kernel(const float* __restrict__ x,
                            const float* __restrict__ w) {
    __shared__ float ws[D * D];
    for (int i = threadIdx.x; i < D * D; i += blockDim.x) ws[i] = w[i];
    __syncthreads();

    int node = blockIdx.x * blockDim.x + threadIdx.x;
    if (node >= N_NODES) return;

    float xr[D];
    const float4* xp = (const float4*)(x + (size_t)node * D);
#pragma unroll
    for (int k4 = 0; k4 < D4; k4++) {
        float4 v = xp[k4];
        xr[k4 * 4 + 0] = v.x;
        xr[k4 * 4 + 1] = v.y;
        xr[k4 * 4 + 2] = v.z;
        xr[k4 * 4 + 3] = v.w;
    }

    float4* outp = (float4*)(g_xw + (size_t)node * D);
#pragma unroll
    for (int j4 = 0; j4 < D4; j4++) {
        float ax = 0.f, ay = 0.f, az = 0.f, aw = 0.f;
#pragma unroll
        for (int k = 0; k < D; k++) {
            float xv = xr[k];
            const float* wrow = ws + k * D + j4 * 4;
            ax = fmaf(xv, wrow[0], ax);
            ay = fmaf(xv, wrow[1], ay);
            az = fmaf(xv, wrow[2], az);
            aw = fmaf(xv, wrow[3], aw);
        }
        outp[j4] = make_float4(ax, ay, az, aw);
    }
}

// ---------------------------------------------------------------------------
// COO scatter: out[dst] += adj_vals[e] * xw[src], via vector RED atomics.
// 12 threads per edge, each handling one float4 column chunk.
// ---------------------------------------------------------------------------
__global__ void scatter_kernel(const int* __restrict__ src,
                               const int* __restrict__ dst,
                               const float* __restrict__ vals,
                               float* __restrict__ out) {
    int tid = blockIdx.x * blockDim.x + threadIdx.x;
    if (tid >= N_EDGES * D4) return;
    int e = tid / D4;
    int c = tid - e * D4;

    int s = __ldg(src + e);
    int d = __ldg(dst + e);
    float a = __ldg(vals + e);

    float4 v = *(const float4*)(g_xw + (size_t)s * D + c * 4);
    float* p = out + (size_t)d * D + c * 4;
    asm volatile("red.global.add.v4.f32 [%0], {%1, %2, %3, %4};"
                 :: "l"(p), "f"(a * v.x), "f"(a * v.y),
                    "f"(a * v.z), "f"(a * v.w)
                 : "memory");
}

// ---------------------------------------------------------------------------
// Finalize: out = relu(out + b), in place, float4-vectorized.
// ---------------------------------------------------------------------------
__global__ void finalize_kernel(float4* __restrict__ out,
                                const float4* __restrict__ b4) {
    int i = blockIdx.x * blockDim.x + threadIdx.x;
    int total = N_NODES * D4;
    if (i >= total) return;
    int c = i % D4;
    float4 bv = b4[c];
    float4 v = out[i];
    v.x = fmaxf(v.x + bv.x, 0.f);
    v.y = fmaxf(v.y + bv.y, 0.f);
    v.z = fmaxf(v.z + bv.z, 0.f);
    v.w = fmaxf(v.w + bv.w, 0.f);
    out[i] = v;
}

extern "C" void kernel_launch(void* const* d_in, const int* in_sizes, int n_in,
                              void* d_out, int out_size) {
    const float* x        = (const float*)d_in[0];
    const float* w        = (const float*)d_in[1];
    const float* b        = (const float*)d_in[2];
    const int*   edge_src = (const int*)d_in[3];
    const int*   edge_dst = (const int*)d_in[4];
    const float* adj_vals = (const float*)d_in[5];
    float* out = (float*)d_out;

    const int threads = 256;

    // 1) zero output (atomics accumulate into it)
    {
        int total = N_NODES * D4;
        zero_kernel<<<(total + threads - 1) / threads, threads>>>((float4*)out);
    }
    // 2) xw = x @ w
    {
        int blocks = (N_NODES + threads - 1) / threads;
        gemm_kernel<<<blocks, threads>>>(x, w);
    }
    // 3) scatter-add over edges
    {
        int total = N_EDGES * D4;
        scatter_kernel<<<(total + threads - 1) / threads, threads>>>(
            edge_src, edge_dst, adj_vals, out);
    }
    // 4) out = relu(out + b)
    {
        int total = N_NODES * D4;
        finalize_kernel<<<(total + threads - 1) / threads, threads>>>(
            (float4*)out, (const float4*)b);
    }
}